// round 3
// baseline (speedup 1.0000x reference)
#include <cuda_runtime.h>
#include <cuda_bf16.h>
#include <cstdint>

// out[t, :] = weight[words[t], :] * mask[words[t]]
// words: (8*2048,) int32, weight: (50257, 768) f32, mask: (50257,) f32
// One CTA per token. 192 threads * float4 = 768 floats = one full row.
// Fully coalesced: 3072B per CTA = 24 x 128B lines read + written.

static constexpr int DIM = 768;
static constexpr int VEC = 4;                // float4
static constexpr int THREADS = DIM / VEC;    // 192

__global__ __launch_bounds__(THREADS, 8)
void embedding_dropout_kernel(const int* __restrict__ words,
                              const float* __restrict__ weight,
                              const float* __restrict__ mask,
                              float* __restrict__ out,
                              int n_tokens)
{
    int t = blockIdx.x;
    if (t >= n_tokens) return;

    int row = __ldg(&words[t]);
    float m = __ldg(&mask[row]);   // same addr across CTA -> L1 broadcast

    const float4* src = reinterpret_cast<const float4*>(weight + (size_t)row * DIM);
    float4*       dst = reinterpret_cast<float4*>(out + (size_t)t * DIM);

    float4 v = __ldg(&src[threadIdx.x]);
    v.x *= m; v.y *= m; v.z *= m; v.w *= m;
    dst[threadIdx.x] = v;
}

extern "C" void kernel_launch(void* const* d_in, const int* in_sizes, int n_in,
                              void* d_out, int out_size)
{
    const int*   words  = (const int*)d_in[0];
    const float* weight = (const float*)d_in[1];
    const float* mask   = (const float*)d_in[2];
    float*       out    = (float*)d_out;

    int n_tokens = in_sizes[0];   // 8 * 2048 = 16384

    embedding_dropout_kernel<<<n_tokens, THREADS>>>(words, weight, mask, out, n_tokens);
}

// round 4
// speedup vs baseline: 1.2937x; 1.2937x over previous
#include <cuda_runtime.h>
#include <cuda_bf16.h>
#include <cstdint>

// out[t, :] = weight[words[t], :] * mask[words[t]]
// words: (16384,) int32, weight: (50257, 768) f32, mask: (50257,) f32
//
// Latency-bound fix: 8 tokens per CTA, front-batched independent loads
// (MLP=8 per thread) instead of 1 token / 1 load per thread.
// Thread i still owns float4 column i of every row -> fully coalesced
// 3072B per token in 24 x 128B lines, read and write.

static constexpr int DIM = 768;
static constexpr int VEC = 4;                 // float4
static constexpr int THREADS = DIM / VEC;     // 192
static constexpr int TOK_PER_CTA = 8;

__global__ __launch_bounds__(THREADS)
void embedding_dropout_k8(const int* __restrict__ words,
                          const float* __restrict__ weight,
                          const float* __restrict__ mask,
                          float* __restrict__ out)
{
    const int t0 = blockIdx.x * TOK_PER_CTA;

    // 8 token ids via two int4 loads; same address across the CTA -> L1 broadcast.
    const int4* wi = reinterpret_cast<const int4*>(words + t0);
    const int4 i0 = __ldg(&wi[0]);
    const int4 i1 = __ldg(&wi[1]);
    const int rows[TOK_PER_CTA] = { i0.x, i0.y, i0.z, i0.w,
                                    i1.x, i1.y, i1.z, i1.w };

    // Front-batch mask loads (independent).
    float m[TOK_PER_CTA];
#pragma unroll
    for (int k = 0; k < TOK_PER_CTA; ++k)
        m[k] = __ldg(&mask[rows[k]]);

    // Front-batch 8 independent LDG.128 gathers -> MLP ~= 8 per thread.
    float4 v[TOK_PER_CTA];
#pragma unroll
    for (int k = 0; k < TOK_PER_CTA; ++k) {
        const float4* src =
            reinterpret_cast<const float4*>(weight + (size_t)rows[k] * DIM);
        v[k] = __ldg(&src[threadIdx.x]);
    }

    // Scale + store (coalesced per token).
#pragma unroll
    for (int k = 0; k < TOK_PER_CTA; ++k) {
        v[k].x *= m[k]; v[k].y *= m[k]; v[k].z *= m[k]; v[k].w *= m[k];
        float4* dst = reinterpret_cast<float4*>(out + (size_t)(t0 + k) * DIM);
        dst[threadIdx.x] = v[k];
    }
}

// Tail kernel: one token per CTA (only used if n_tokens % 8 != 0).
__global__ __launch_bounds__(THREADS)
void embedding_dropout_k1(const int* __restrict__ words,
                          const float* __restrict__ weight,
                          const float* __restrict__ mask,
                          float* __restrict__ out,
                          int t_base, int n_tokens)
{
    const int t = t_base + blockIdx.x;
    if (t >= n_tokens) return;
    const int row = __ldg(&words[t]);
    const float m = __ldg(&mask[row]);
    const float4* src = reinterpret_cast<const float4*>(weight + (size_t)row * DIM);
    float4 v = __ldg(&src[threadIdx.x]);
    v.x *= m; v.y *= m; v.z *= m; v.w *= m;
    reinterpret_cast<float4*>(out + (size_t)t * DIM)[threadIdx.x] = v;
}

extern "C" void kernel_launch(void* const* d_in, const int* in_sizes, int n_in,
                              void* d_out, int out_size)
{
    const int*   words  = (const int*)d_in[0];
    const float* weight = (const float*)d_in[1];
    const float* mask   = (const float*)d_in[2];
    float*       out    = (float*)d_out;

    const int n_tokens = in_sizes[0];            // 16384
    const int n_full   = n_tokens / TOK_PER_CTA; // 2048
    const int tail     = n_tokens - n_full * TOK_PER_CTA;

    if (n_full > 0)
        embedding_dropout_k8<<<n_full, THREADS>>>(words, weight, mask, out);
    if (tail > 0)
        embedding_dropout_k1<<<tail, THREADS>>>(words, weight, mask, out,
                                                n_full * TOK_PER_CTA, n_tokens);
}